// round 1
// baseline (speedup 1.0000x reference)
#include <cuda_runtime.h>
#include <math.h>

// Problem constants
#define NB   8192
#define DFT  256
#define RNK  16
#define AH   512

// ---------------------------------------------------------------------------
// Scratch (device globals: allocation-free per harness rules)
// ---------------------------------------------------------------------------
__device__ float g_p [NB * DFT];   // relu(LN(h_g  @ Wg.T + bg))
__device__ float d2_p[NB * DFT];   // relu(LN(h_2d @ W2.T + b2))
__device__ float d3_p[NB * DFT];   // relu(LN(h_3d @ W3.T + b3))
__device__ float a1_g[NB * AH];    // relu(h_cat @ Wa1.T + ba1)
__device__ float beta_g[NB * RNK]; // softmax logits

// ---------------------------------------------------------------------------
// Generic 128x128x16 SGEMM:  C[M,N] = A[M,K] @ W[N,K]^T + bias, optional ReLU.
// A may be a concat of up to 3 sources (boundaries K0, K01 — multiples of 16).
// M = 8192 fixed by grid; N % 128 == 0; K % 16 == 0.
// ---------------------------------------------------------------------------
__global__ __launch_bounds__(256)
void sgemm128(const float* __restrict__ A0, const float* __restrict__ A1,
              const float* __restrict__ A2, int K0, int K01,
              const float* __restrict__ W,  const float* __restrict__ bias,
              float* __restrict__ C, int N, int K, int relu)
{
    __shared__ __align__(16) float As[16][132];  // k-major, padded
    __shared__ __align__(16) float Bs[16][132];

    const int bm = blockIdx.y * 128;
    const int bn = blockIdx.x * 128;
    const int t  = threadIdx.x;
    const int tx = t & 15;        // 16 col-threads  (TN=8)
    const int ty = t >> 4;        // 16 row-threads  (TM=8)
    const int lrow = t >> 2;      // 0..63 loader row
    const int lk4  = (t & 3) << 2;

    float acc[8][8] = {};

    for (int k0 = 0; k0 < K; k0 += 16) {
        const int k = k0 + lk4;
        #pragma unroll
        for (int it = 0; it < 2; ++it) {
            const int m  = lrow + (it << 6);
            const int gm = bm + m;
            float4 v;
            if (k < K0)       v = *(const float4*)(A0 + (size_t)gm * K0 + k);
            else if (k < K01) v = *(const float4*)(A1 + (size_t)gm * (K01 - K0) + (k - K0));
            else              v = *(const float4*)(A2 + (size_t)gm * (K - K01) + (k - K01));
            As[lk4 + 0][m] = v.x; As[lk4 + 1][m] = v.y;
            As[lk4 + 2][m] = v.z; As[lk4 + 3][m] = v.w;
            float4 w = *(const float4*)(W + (size_t)(bn + m) * K + k);
            Bs[lk4 + 0][m] = w.x; Bs[lk4 + 1][m] = w.y;
            Bs[lk4 + 2][m] = w.z; Bs[lk4 + 3][m] = w.w;
        }
        __syncthreads();
        #pragma unroll
        for (int kk = 0; kk < 16; ++kk) {
            float ra[8], rb[8];
            *(float4*)(ra)     = *(const float4*)&As[kk][ty * 8];
            *(float4*)(ra + 4) = *(const float4*)&As[kk][ty * 8 + 4];
            *(float4*)(rb)     = *(const float4*)&Bs[kk][tx * 8];
            *(float4*)(rb + 4) = *(const float4*)&Bs[kk][tx * 8 + 4];
            #pragma unroll
            for (int i = 0; i < 8; ++i)
                #pragma unroll
                for (int j = 0; j < 8; ++j)
                    acc[i][j] = fmaf(ra[i], rb[j], acc[i][j]);
        }
        __syncthreads();
    }

    #pragma unroll
    for (int i = 0; i < 8; ++i) {
        const int gm = bm + ty * 8 + i;
        #pragma unroll
        for (int j = 0; j < 8; ++j) {
            const int gn = bn + tx * 8 + j;
            float v = acc[i][j] + bias[gn];
            if (relu) v = fmaxf(v, 0.f);
            C[(size_t)gm * N + gn] = v;
        }
    }
}

// ---------------------------------------------------------------------------
// LayerNorm + ReLU, in place, one block per row. grid.x = 3*8192.
// ---------------------------------------------------------------------------
__global__ __launch_bounds__(256)
void ln_relu(const float* __restrict__ lgw, const float* __restrict__ lgb,
             const float* __restrict__ l2w, const float* __restrict__ l2b,
             const float* __restrict__ l3w, const float* __restrict__ l3b)
{
    const int idx = blockIdx.x;
    const int mod = idx >> 13;       // / 8192
    const int row = idx & 8191;
    float* buf; const float* w; const float* b;
    if (mod == 0)      { buf = g_p;  w = lgw; b = lgb; }
    else if (mod == 1) { buf = d2_p; w = l2w; b = l2b; }
    else               { buf = d3_p; w = l3w; b = l3b; }

    const int t = threadIdx.x;
    const float v = buf[(size_t)row * DFT + t];
    float s = v, q = v * v;
    #pragma unroll
    for (int o = 16; o > 0; o >>= 1) {
        s += __shfl_down_sync(0xffffffffu, s, o);
        q += __shfl_down_sync(0xffffffffu, q, o);
    }
    __shared__ float ss[8], qq[8];
    __shared__ float mu_s, rstd_s;
    if ((t & 31) == 0) { ss[t >> 5] = s; qq[t >> 5] = q; }
    __syncthreads();
    if (t == 0) {
        float S = 0.f, Q = 0.f;
        #pragma unroll
        for (int i = 0; i < 8; ++i) { S += ss[i]; Q += qq[i]; }
        const float mu  = S * (1.f / 256.f);
        const float var = Q * (1.f / 256.f) - mu * mu;
        mu_s = mu; rstd_s = rsqrtf(var + 1e-5f);
    }
    __syncthreads();
    const float o = (v - mu_s) * rstd_s * w[t] + b[t];
    buf[(size_t)row * DFT + t] = fmaxf(o, 0.f);
}

// ---------------------------------------------------------------------------
// beta = softmax(a1 @ Wa2.T + ba2).  One block (128 thr) per row.
// ---------------------------------------------------------------------------
__global__ __launch_bounds__(128)
void beta_kernel(const float* __restrict__ Wa2, const float* __restrict__ ba2)
{
    const int row = blockIdx.x;
    __shared__ float sh[AH];
    __shared__ float logits[RNK];
    const int t = threadIdx.x;
    #pragma unroll
    for (int i = 0; i < 4; ++i)
        sh[t + i * 128] = a1_g[(size_t)row * AH + t + i * 128];
    __syncthreads();

    const int r = t >> 3;   // 0..15
    const int l = t & 7;
    float s = 0.f;
    for (int j = l; j < AH; j += 8)
        s = fmaf(sh[j], Wa2[r * AH + j], s);
    s += __shfl_down_sync(0xffffffffu, s, 4);
    s += __shfl_down_sync(0xffffffffu, s, 2);
    s += __shfl_down_sync(0xffffffffu, s, 1);
    if (l == 0) logits[r] = s + ba2[r];
    __syncthreads();
    if (t == 0) {
        float mx = logits[0];
        #pragma unroll
        for (int i = 1; i < RNK; ++i) mx = fmaxf(mx, logits[i]);
        float e[RNK], den = 0.f;
        #pragma unroll
        for (int i = 0; i < RNK; ++i) { e[i] = expf(logits[i] - mx); den += e[i]; }
        const float inv = 1.f / den;
        #pragma unroll
        for (int i = 0; i < RNK; ++i)
            beta_g[(size_t)row * RNK + i] = e[i] * inv;
    }
}

// ---------------------------------------------------------------------------
// Fused rank expansion + trilinear product + beta contraction.
//   z[b,d] = sum_r beta[b,r] * (g[b]·U[r*256+d]) * (d2[b]·V[..]) * (d3[b]·S[..])
// Block tile: 32 batch rows x 64 d-cols; threads 128 (8 ty x 16 tx), TM=TN=4.
// z_r (3x[8192,4096] = 384MB) is never materialized.
// ---------------------------------------------------------------------------
__global__ __launch_bounds__(128)
void fuse_trilinear(const float* __restrict__ U, const float* __restrict__ V,
                    const float* __restrict__ S, float* __restrict__ z)
{
    __shared__ __align__(16) float As[32][33];   // activation tile, row-major
    __shared__ __align__(16) float Bs[32][68];   // weight tile, k-major [k][col]
    __shared__ float Bes[RNK][32];               // beta tile [r][row]

    const int bm = blockIdx.y << 5;   // batch tile
    const int bn = blockIdx.x << 6;   // feature tile
    const int t  = threadIdx.x;
    const int tx = t & 15;
    const int ty = t >> 4;

    for (int i = t; i < RNK * 32; i += 128) {
        const int r = i >> 5, row = i & 31;
        Bes[r][row] = beta_g[(size_t)(bm + row) * RNK + r];
    }

    float zacc[4][4] = {};

    for (int r = 0; r < RNK; ++r) {
        float fr[3][4][4];
        #pragma unroll
        for (int m = 0; m < 3; ++m) {
            const float* __restrict__ Wm = (m == 0) ? U : (m == 1) ? V : S;
            const float* __restrict__ Am = (m == 0) ? g_p : (m == 1) ? d2_p : d3_p;
            #pragma unroll
            for (int i = 0; i < 4; ++i)
                #pragma unroll
                for (int j = 0; j < 4; ++j) fr[m][i][j] = 0.f;

            for (int k0 = 0; k0 < DFT; k0 += 32) {
                __syncthreads();   // protect previous tile (and Bes preload)
                // activation tile: 32 rows x 32 k = 1024 floats
                #pragma unroll
                for (int i2 = 0; i2 < 2; ++i2) {
                    const int i   = t + i2 * 128;
                    const int row = i >> 3, k4 = (i & 7) << 2;
                    float4 a = *(const float4*)(Am + (size_t)(bm + row) * DFT + k0 + k4);
                    As[row][k4 + 0] = a.x; As[row][k4 + 1] = a.y;
                    As[row][k4 + 2] = a.z; As[row][k4 + 3] = a.w;
                }
                // weight tile: 64 cols x 32 k, stored k-major for vector reads
                #pragma unroll
                for (int i2 = 0; i2 < 4; ++i2) {
                    const int i   = t + i2 * 128;
                    const int col = i >> 3, k4 = (i & 7) << 2;
                    float4 u = *(const float4*)
                        (Wm + (size_t)(r * DFT + bn + col) * DFT + k0 + k4);
                    Bs[k4 + 0][col] = u.x; Bs[k4 + 1][col] = u.y;
                    Bs[k4 + 2][col] = u.z; Bs[k4 + 3][col] = u.w;
                }
                __syncthreads();
                #pragma unroll 8
                for (int k = 0; k < 32; ++k) {
                    float rb[4];
                    *(float4*)rb = *(const float4*)&Bs[k][tx * 4];
                    #pragma unroll
                    for (int i = 0; i < 4; ++i) {
                        const float ra = As[ty * 4 + i][k];
                        #pragma unroll
                        for (int j = 0; j < 4; ++j)
                            fr[m][i][j] = fmaf(ra, rb[j], fr[m][i][j]);
                    }
                }
            }
        }
        #pragma unroll
        for (int i = 0; i < 4; ++i) {
            const float b = Bes[r][ty * 4 + i];
            #pragma unroll
            for (int j = 0; j < 4; ++j)
                zacc[i][j] = fmaf(b * fr[0][i][j] * fr[1][i][j], fr[2][i][j],
                                  zacc[i][j]);
        }
    }

    #pragma unroll
    for (int i = 0; i < 4; ++i) {
        const int gm = bm + ty * 4 + i;
        #pragma unroll
        for (int j = 0; j < 4; ++j)
            z[(size_t)gm * DFT + bn + tx * 4 + j] = zacc[i][j];
    }
}

// ---------------------------------------------------------------------------
// Host launcher (graph-capturable: kernel launches only)
// ---------------------------------------------------------------------------
extern "C" void kernel_launch(void* const* d_in, const int* in_sizes, int n_in,
                              void* d_out, int out_size)
{
    const float* h_g  = (const float*)d_in[0];
    const float* h_2d = (const float*)d_in[1];
    const float* h_3d = (const float*)d_in[2];
    const float* Wg   = (const float*)d_in[3];
    const float* bg   = (const float*)d_in[4];
    const float* W2   = (const float*)d_in[5];
    const float* b2   = (const float*)d_in[6];
    const float* W3   = (const float*)d_in[7];
    const float* b3   = (const float*)d_in[8];
    const float* lgw  = (const float*)d_in[9];
    const float* lgb  = (const float*)d_in[10];
    const float* l2w  = (const float*)d_in[11];
    const float* l2b  = (const float*)d_in[12];
    const float* l3w  = (const float*)d_in[13];
    const float* l3b  = (const float*)d_in[14];
    const float* U    = (const float*)d_in[15];
    const float* V    = (const float*)d_in[16];
    const float* S    = (const float*)d_in[17];
    const float* Wa1  = (const float*)d_in[18];
    const float* ba1  = (const float*)d_in[19];
    const float* Wa2  = (const float*)d_in[20];
    const float* ba2  = (const float*)d_in[21];
    float* z = (float*)d_out;

    float *gp, *d2p, *d3p, *a1p;
    cudaGetSymbolAddress((void**)&gp,  g_p);
    cudaGetSymbolAddress((void**)&d2p, d2_p);
    cudaGetSymbolAddress((void**)&d3p, d3_p);
    cudaGetSymbolAddress((void**)&a1p, a1_g);

    const dim3 blk(256);
    // modality projections (bias in epilogue; LN afterwards)
    sgemm128<<<dim3(2, 64), blk>>>(h_g,  h_g,  h_g,  512,  512,  Wg, bg, gp,  256, 512,  0);
    sgemm128<<<dim3(2, 64), blk>>>(h_2d, h_2d, h_2d, 768,  768,  W2, b2, d2p, 256, 768,  0);
    sgemm128<<<dim3(2, 64), blk>>>(h_3d, h_3d, h_3d, 1024, 1024, W3, b3, d3p, 256, 1024, 0);
    ln_relu<<<3 * NB, 256>>>(lgw, lgb, l2w, l2b, l3w, l3b);
    // attention MLP layer 1 on raw concat (independent of LN path)
    sgemm128<<<dim3(4, 64), blk>>>(h_g, h_2d, h_3d, 512, 1280, Wa1, ba1, a1p, 512, 2304, 1);
    beta_kernel<<<NB, 128>>>(Wa2, ba2);
    // fused rank expansion + trilinear + beta contraction -> z
    fuse_trilinear<<<dim3(4, 256), 128>>>(U, V, S, z);
}

// round 3
// speedup vs baseline: 1.2811x; 1.2811x over previous
#include <cuda_runtime.h>
#include <cuda_bf16.h>
#include <stdint.h>
#include <math.h>

// Problem constants
#define NB   8192
#define DFT  256
#define RNK  16
#define AH   512
#define WSZ  (RNK * DFT * DFT)   // 1048576 elements per rank-expansion weight

// ---------------------------------------------------------------------------
// Scratch (device globals: allocation-free per harness rules)
// ---------------------------------------------------------------------------
__device__ float g_p [NB * DFT];   // LN inputs (proj outputs)
__device__ float d2_p[NB * DFT];
__device__ float d3_p[NB * DFT];
__device__ float a1_g[NB * AH];    // relu(h_cat @ Wa1.T + ba1)
__device__ float beta_g[NB * RNK]; // softmax weights

// bf16 hi/lo splits for the tensor-core trilinear kernel
__device__ __nv_bfloat16 A_hi[3][NB * DFT];
__device__ __nv_bfloat16 A_lo[3][NB * DFT];
__device__ __nv_bfloat16 W_hi[3][WSZ];
__device__ __nv_bfloat16 W_lo[3][WSZ];

// ---------------------------------------------------------------------------
// Generic 128x128x16 fp32 SGEMM:  C = A @ W^T + bias, optional ReLU.
// A may be a concat of up to 3 sources (boundaries K0, K01).
// ---------------------------------------------------------------------------
__global__ __launch_bounds__(256)
void sgemm128(const float* __restrict__ A0, const float* __restrict__ A1,
              const float* __restrict__ A2, int K0, int K01,
              const float* __restrict__ W,  const float* __restrict__ bias,
              float* __restrict__ C, int N, int K, int relu)
{
    __shared__ __align__(16) float As[16][132];
    __shared__ __align__(16) float Bs[16][132];

    const int bm = blockIdx.y * 128;
    const int bn = blockIdx.x * 128;
    const int t  = threadIdx.x;
    const int tx = t & 15;
    const int ty = t >> 4;
    const int lrow = t >> 2;
    const int lk4  = (t & 3) << 2;

    float acc[8][8] = {};

    for (int k0 = 0; k0 < K; k0 += 16) {
        const int k = k0 + lk4;
        #pragma unroll
        for (int it = 0; it < 2; ++it) {
            const int m  = lrow + (it << 6);
            const int gm = bm + m;
            float4 v;
            if (k < K0)       v = *(const float4*)(A0 + (size_t)gm * K0 + k);
            else if (k < K01) v = *(const float4*)(A1 + (size_t)gm * (K01 - K0) + (k - K0));
            else              v = *(const float4*)(A2 + (size_t)gm * (K - K01) + (k - K01));
            As[lk4 + 0][m] = v.x; As[lk4 + 1][m] = v.y;
            As[lk4 + 2][m] = v.z; As[lk4 + 3][m] = v.w;
            float4 w = *(const float4*)(W + (size_t)(bn + m) * K + k);
            Bs[lk4 + 0][m] = w.x; Bs[lk4 + 1][m] = w.y;
            Bs[lk4 + 2][m] = w.z; Bs[lk4 + 3][m] = w.w;
        }
        __syncthreads();
        #pragma unroll
        for (int kk = 0; kk < 16; ++kk) {
            float ra[8], rb[8];
            *(float4*)(ra)     = *(const float4*)&As[kk][ty * 8];
            *(float4*)(ra + 4) = *(const float4*)&As[kk][ty * 8 + 4];
            *(float4*)(rb)     = *(const float4*)&Bs[kk][tx * 8];
            *(float4*)(rb + 4) = *(const float4*)&Bs[kk][tx * 8 + 4];
            #pragma unroll
            for (int i = 0; i < 8; ++i)
                #pragma unroll
                for (int j = 0; j < 8; ++j)
                    acc[i][j] = fmaf(ra[i], rb[j], acc[i][j]);
        }
        __syncthreads();
    }

    #pragma unroll
    for (int i = 0; i < 8; ++i) {
        const int gm = bm + ty * 8 + i;
        #pragma unroll
        for (int j = 0; j < 8; ++j) {
            const int gn = bn + tx * 8 + j;
            float v = acc[i][j] + bias[gn];
            if (relu) v = fmaxf(v, 0.f);
            C[(size_t)gm * N + gn] = v;
        }
    }
}

// ---------------------------------------------------------------------------
// LayerNorm + ReLU + bf16 hi/lo split. One block per row; grid.x = 3*8192.
// ---------------------------------------------------------------------------
__global__ __launch_bounds__(256)
void ln_relu(const float* __restrict__ lgw, const float* __restrict__ lgb,
             const float* __restrict__ l2w, const float* __restrict__ l2b,
             const float* __restrict__ l3w, const float* __restrict__ l3b)
{
    const int idx = blockIdx.x;
    const int mod = idx >> 13;
    const int row = idx & 8191;
    const float* buf; const float* w; const float* b;
    if (mod == 0)      { buf = g_p;  w = lgw; b = lgb; }
    else if (mod == 1) { buf = d2_p; w = l2w; b = l2b; }
    else               { buf = d3_p; w = l3w; b = l3b; }

    const int t = threadIdx.x;
    const float v = buf[(size_t)row * DFT + t];
    float s = v, q = v * v;
    #pragma unroll
    for (int o = 16; o > 0; o >>= 1) {
        s += __shfl_down_sync(0xffffffffu, s, o);
        q += __shfl_down_sync(0xffffffffu, q, o);
    }
    __shared__ float ss[8], qq[8];
    __shared__ float mu_s, rstd_s;
    if ((t & 31) == 0) { ss[t >> 5] = s; qq[t >> 5] = q; }
    __syncthreads();
    if (t == 0) {
        float S = 0.f, Q = 0.f;
        #pragma unroll
        for (int i = 0; i < 8; ++i) { S += ss[i]; Q += qq[i]; }
        const float mu  = S * (1.f / 256.f);
        const float var = Q * (1.f / 256.f) - mu * mu;
        mu_s = mu; rstd_s = rsqrtf(var + 1e-5f);
    }
    __syncthreads();
    const float o  = (v - mu_s) * rstd_s * w[t] + b[t];
    const float oo = fmaxf(o, 0.f);
    const __nv_bfloat16 hi = __float2bfloat16(oo);
    A_hi[mod][(size_t)row * DFT + t] = hi;
    A_lo[mod][(size_t)row * DFT + t] = __float2bfloat16(oo - __bfloat162float(hi));
}

// ---------------------------------------------------------------------------
// Weight hi/lo split (elementwise).
// ---------------------------------------------------------------------------
__global__ __launch_bounds__(256)
void splitw(const float* __restrict__ src, __nv_bfloat16* __restrict__ hi,
            __nv_bfloat16* __restrict__ lo, int n)
{
    const int i = blockIdx.x * 256 + threadIdx.x;
    if (i < n) {
        const float x = src[i];
        const __nv_bfloat16 h = __float2bfloat16(x);
        hi[i] = h;
        lo[i] = __float2bfloat16(x - __bfloat162float(h));
    }
}

// ---------------------------------------------------------------------------
// beta = softmax(a1 @ Wa2.T + ba2).  One block (128 thr) per row.
// ---------------------------------------------------------------------------
__global__ __launch_bounds__(128)
void beta_kernel(const float* __restrict__ Wa2, const float* __restrict__ ba2)
{
    const int row = blockIdx.x;
    __shared__ float sh[AH];
    __shared__ float logits[RNK];
    const int t = threadIdx.x;
    #pragma unroll
    for (int i = 0; i < 4; ++i)
        sh[t + i * 128] = a1_g[(size_t)row * AH + t + i * 128];
    __syncthreads();

    const int r = t >> 3;
    const int l = t & 7;
    float s = 0.f;
    for (int j = l; j < AH; j += 8)
        s = fmaf(sh[j], Wa2[r * AH + j], s);
    s += __shfl_down_sync(0xffffffffu, s, 4);
    s += __shfl_down_sync(0xffffffffu, s, 2);
    s += __shfl_down_sync(0xffffffffu, s, 1);
    if (l == 0) logits[r] = s + ba2[r];
    __syncthreads();
    if (t == 0) {
        float mx = logits[0];
        #pragma unroll
        for (int i = 1; i < RNK; ++i) mx = fmaxf(mx, logits[i]);
        float e[RNK], den = 0.f;
        #pragma unroll
        for (int i = 0; i < RNK; ++i) { e[i] = expf(logits[i] - mx); den += e[i]; }
        const float inv = 1.f / den;
        #pragma unroll
        for (int i = 0; i < RNK; ++i)
            beta_g[(size_t)row * RNK + i] = e[i] * inv;
    }
}

// ---------------------------------------------------------------------------
// Tensor-core fused trilinear:
//   z[b,d] = sum_r beta[b,r] * (g·U_r)[b,d] * (d2·V_r)[b,d] * (d3·S_r)[b,d]
// bf16 2-term split (3 MMAs: hh + hl + lh) -> ~1.5e-5 rel error, fp32 acc.
// Block: 64 batch x 64 feat, 8 warps (4x2), warp tile 16x32.
// 192 stages (16 r x 3 m x 4 k-chunks of 64), 3-deep cp.async ring.
// ---------------------------------------------------------------------------
#define KC     64
#define SPITCH 72                 // smem row pitch (elements); conflict-free
#define S1     (64 * SPITCH)      // elems per array per stage
#define NSTAGE (RNK * 3 * 4)      // 192

#define MMA_BF16(c, a, b)                                                     \
  asm volatile("mma.sync.aligned.m16n8k16.row.col.f32.bf16.bf16.f32 "         \
               "{%0,%1,%2,%3}, {%4,%5,%6,%7}, {%8,%9}, {%0,%1,%2,%3};\n"      \
               : "+f"((c)[0]), "+f"((c)[1]), "+f"((c)[2]), "+f"((c)[3])       \
               : "r"((a)[0]), "r"((a)[1]), "r"((a)[2]), "r"((a)[3]),          \
                 "r"((b)[0]), "r"((b)[1]))

__global__ __launch_bounds__(256)
void fuse_mma(float* __restrict__ z)
{
    extern __shared__ __align__(16) char smraw[];
    __nv_bfloat16* sm = (__nv_bfloat16*)smraw;
    __shared__ float Bes[64][17];

    const int bm   = blockIdx.y << 6;
    const int bn   = blockIdx.x << 6;
    const int tid  = threadIdx.x;
    const int lane = tid & 31, wid = tid >> 5;
    const int wm   = wid & 3,  wn  = wid >> 2;   // warp grid 4 x 2
    const int g    = lane >> 2, tg = lane & 3;

    // beta tile for this batch block
    for (int i = tid; i < 64 * RNK; i += 256)
        Bes[i >> 4][i & 15] = beta_g[(size_t)(bm + (i >> 4)) * RNK + (i & 15)];

    // loader role: 4 arrays (Ah,Al,Bh,Bl) x 64 rows; each thread copies one row
    const int arr  = tid >> 6;
    const int lrow = tid & 63;

    auto issue = [&](int s) {
        const int r2 = s / 12;
        const int m2 = (s % 12) >> 2;
        const int kc = (s & 3) << 6;
        const __nv_bfloat16* gsrc;
        if (arr == 0)      gsrc = &A_hi[m2][(size_t)(bm + lrow) * DFT + kc];
        else if (arr == 1) gsrc = &A_lo[m2][(size_t)(bm + lrow) * DFT + kc];
        else if (arr == 2) gsrc = &W_hi[m2][(size_t)(r2 * DFT + bn + lrow) * DFT + kc];
        else               gsrc = &W_lo[m2][(size_t)(r2 * DFT + bn + lrow) * DFT + kc];
        __nv_bfloat16* dst = sm + (size_t)(s % 3) * 4 * S1 + arr * S1 + lrow * SPITCH;
        uint32_t sa = (uint32_t)__cvta_generic_to_shared(dst);
        #pragma unroll
        for (int q = 0; q < 8; ++q)
            asm volatile("cp.async.cg.shared.global [%0], [%1], 16;\n"
                         :: "r"(sa + q * 16), "l"(gsrc + q * 8));
    };

    issue(0);
    asm volatile("cp.async.commit_group;\n" ::: "memory");

    float acc[3][4][4];
    float zacc[4][4];
    #pragma unroll
    for (int t = 0; t < 4; ++t)
        #pragma unroll
        for (int e = 0; e < 4; ++e) zacc[t][e] = 0.f;
    #pragma unroll
    for (int mm = 0; mm < 3; ++mm)
        #pragma unroll
        for (int t = 0; t < 4; ++t)
            #pragma unroll
            for (int e = 0; e < 4; ++e) acc[mm][t][e] = 0.f;

    const int ar0 = (wm * 16 + g) * SPITCH;
    const int ar1 = (wm * 16 + g + 8) * SPITCH;
    const int cofs = tg * 2;

    int s = 0;
    for (int r = 0; r < RNK; ++r) {
        #pragma unroll
        for (int mI = 0; mI < 3; ++mI) {
            for (int c = 0; c < 4; ++c, ++s) {
                if (s + 1 < NSTAGE) issue(s + 1);
                asm volatile("cp.async.commit_group;\n" ::: "memory");
                asm volatile("cp.async.wait_group 1;\n" ::: "memory");
                __syncthreads();

                const __nv_bfloat16* base = sm + (size_t)(s % 3) * 4 * S1;
                const __nv_bfloat16* Ah = base;
                const __nv_bfloat16* Al = base + S1;
                const __nv_bfloat16* Bh = base + 2 * S1;
                const __nv_bfloat16* Bl = base + 3 * S1;

                #pragma unroll
                for (int ks = 0; ks < KC; ks += 16) {
                    uint32_t ahi[4], alo[4];
                    ahi[0] = *(const uint32_t*)(Ah + ar0 + ks + cofs);
                    ahi[1] = *(const uint32_t*)(Ah + ar1 + ks + cofs);
                    ahi[2] = *(const uint32_t*)(Ah + ar0 + ks + cofs + 8);
                    ahi[3] = *(const uint32_t*)(Ah + ar1 + ks + cofs + 8);
                    alo[0] = *(const uint32_t*)(Al + ar0 + ks + cofs);
                    alo[1] = *(const uint32_t*)(Al + ar1 + ks + cofs);
                    alo[2] = *(const uint32_t*)(Al + ar0 + ks + cofs + 8);
                    alo[3] = *(const uint32_t*)(Al + ar1 + ks + cofs + 8);

                    uint32_t bh[4][2], bl[4][2];
                    #pragma unroll
                    for (int t = 0; t < 4; ++t) {
                        const int nr = (wn * 32 + t * 8 + g) * SPITCH;
                        bh[t][0] = *(const uint32_t*)(Bh + nr + ks + cofs);
                        bh[t][1] = *(const uint32_t*)(Bh + nr + ks + cofs + 8);
                        bl[t][0] = *(const uint32_t*)(Bl + nr + ks + cofs);
                        bl[t][1] = *(const uint32_t*)(Bl + nr + ks + cofs + 8);
                    }
                    #pragma unroll
                    for (int t = 0; t < 4; ++t) MMA_BF16(acc[mI][t], ahi, bh[t]);
                    #pragma unroll
                    for (int t = 0; t < 4; ++t) MMA_BF16(acc[mI][t], ahi, bl[t]);
                    #pragma unroll
                    for (int t = 0; t < 4; ++t) MMA_BF16(acc[mI][t], alo, bh[t]);
                }
            }
        }
        // combine rank r: z += beta_r * f_g * f_2 * f_3 (register-local)
        {
            const float b0 = Bes[wm * 16 + g][r];
            const float b1 = Bes[wm * 16 + g + 8][r];
            #pragma unroll
            for (int t = 0; t < 4; ++t) {
                zacc[t][0] += b0 * acc[0][t][0] * acc[1][t][0] * acc[2][t][0];
                zacc[t][1] += b0 * acc[0][t][1] * acc[1][t][1] * acc[2][t][1];
                zacc[t][2] += b1 * acc[0][t][2] * acc[1][t][2] * acc[2][t][2];
                zacc[t][3] += b1 * acc[0][t][3] * acc[1][t][3] * acc[2][t][3];
            }
            #pragma unroll
            for (int mm = 0; mm < 3; ++mm)
                #pragma unroll
                for (int t = 0; t < 4; ++t)
                    #pragma unroll
                    for (int e = 0; e < 4; ++e) acc[mm][t][e] = 0.f;
        }
    }

    // epilogue
    const int row0 = bm + wm * 16 + g;
    #pragma unroll
    for (int t = 0; t < 4; ++t) {
        const int col = bn + wn * 32 + t * 8 + cofs;
        *(float2*)&z[(size_t)row0 * DFT + col]       = make_float2(zacc[t][0], zacc[t][1]);
        *(float2*)&z[(size_t)(row0 + 8) * DFT + col] = make_float2(zacc[t][2], zacc[t][3]);
    }
}

// ---------------------------------------------------------------------------
// Host launcher (graph-capturable)
// ---------------------------------------------------------------------------
extern "C" void kernel_launch(void* const* d_in, const int* in_sizes, int n_in,
                              void* d_out, int out_size)
{
    const float* h_g  = (const float*)d_in[0];
    const float* h_2d = (const float*)d_in[1];
    const float* h_3d = (const float*)d_in[2];
    const float* Wg   = (const float*)d_in[3];
    const float* bg   = (const float*)d_in[4];
    const float* W2   = (const float*)d_in[5];
    const float* b2   = (const float*)d_in[6];
    const float* W3   = (const float*)d_in[7];
    const float* b3   = (const float*)d_in[8];
    const float* lgw  = (const float*)d_in[9];
    const float* lgb  = (const float*)d_in[10];
    const float* l2w  = (const float*)d_in[11];
    const float* l2b  = (const float*)d_in[12];
    const float* l3w  = (const float*)d_in[13];
    const float* l3b  = (const float*)d_in[14];
    const float* U    = (const float*)d_in[15];
    const float* V    = (const float*)d_in[16];
    const float* S    = (const float*)d_in[17];
    const float* Wa1  = (const float*)d_in[18];
    const float* ba1  = (const float*)d_in[19];
    const float* Wa2  = (const float*)d_in[20];
    const float* ba2  = (const float*)d_in[21];
    float* z = (float*)d_out;

    float *gp, *d2p, *d3p, *a1p;
    cudaGetSymbolAddress((void**)&gp,  g_p);
    cudaGetSymbolAddress((void**)&d2p, d2_p);
    cudaGetSymbolAddress((void**)&d3p, d3_p);
    cudaGetSymbolAddress((void**)&a1p, a1_g);
    __nv_bfloat16 *whi, *wlo;
    cudaGetSymbolAddress((void**)&whi, W_hi);
    cudaGetSymbolAddress((void**)&wlo, W_lo);

    static int smem_set = 0;
    if (!smem_set) {
        cudaFuncSetAttribute(fuse_mma, cudaFuncAttributeMaxDynamicSharedMemorySize,
                             3 * 4 * S1 * (int)sizeof(__nv_bfloat16));
        smem_set = 1;
    }

    const dim3 blk(256);
    // modality projections (fp32 GEMM; LN after)
    sgemm128<<<dim3(2, 64), blk>>>(h_g,  h_g,  h_g,  512,  512,  Wg, bg, gp,  256, 512,  0);
    sgemm128<<<dim3(2, 64), blk>>>(h_2d, h_2d, h_2d, 768,  768,  W2, b2, d2p, 256, 768,  0);
    sgemm128<<<dim3(2, 64), blk>>>(h_3d, h_3d, h_3d, 1024, 1024, W3, b3, d3p, 256, 1024, 0);
    ln_relu<<<3 * NB, 256>>>(lgw, lgb, l2w, l2b, l3w, l3b);
    // attention MLP layer 1 on raw concat
    sgemm128<<<dim3(4, 64), blk>>>(h_g, h_2d, h_3d, 512, 1280, Wa1, ba1, a1p, 512, 2304, 1);
    beta_kernel<<<NB, 128>>>(Wa2, ba2);
    // weight hi/lo splits
    splitw<<<WSZ / 256, 256>>>(U, whi + 0 * WSZ, wlo + 0 * WSZ, WSZ);
    splitw<<<WSZ / 256, 256>>>(V, whi + 1 * WSZ, wlo + 1 * WSZ, WSZ);
    splitw<<<WSZ / 256, 256>>>(S, whi + 2 * WSZ, wlo + 2 * WSZ, WSZ);
    // fused tensor-core trilinear + beta contraction
    fuse_mma<<<dim3(4, 128), 256, 3 * 4 * S1 * (int)sizeof(__nv_bfloat16)>>>(z);
}